// round 13
// baseline (speedup 1.0000x reference)
#include <cuda_runtime.h>
#include <cuda_bf16.h>

#define Bz 32768
#define Dd 2048
#define Ld 64
#define NC 64

typedef unsigned long long ull;
typedef unsigned int uint;

static __device__ float g_Cq[NC * Dd];
static __device__ float g_Esq[NC];
static __device__ int   g_k[Bz];
static __device__ __nv_bfloat16 g_Wth[Ld * Dd];  // W_enc^T hi  [64][2048]
static __device__ __nv_bfloat16 g_Wtl[Ld * Dd];  // W_enc^T lo

union F2U { ull u; float2 f; };

__device__ __forceinline__ void ffma2(ull& d, ull a, ull b) {
    asm("fma.rn.f32x2 %0, %1, %2, %0;" : "+l"(d) : "l"(a), "l"(b));
}
__device__ __forceinline__ ull pack2(float a) {
    ull r; asm("mov.b64 %0, {%1, %1};" : "=l"(r) : "f"(a)); return r;
}
__device__ __forceinline__ void cp16(void* s, const void* g) {
    uint sa = (uint)__cvta_generic_to_shared(s);
    asm volatile("cp.async.cg.shared.global [%0], [%1], 16;" :: "r"(sa), "l"(g));
}
#define CP_COMMIT asm volatile("cp.async.commit_group;")
#define CP_WAIT0  asm volatile("cp.async.wait_group 0;")

// packed bf16x2: low half = a, high half = b
__device__ __forceinline__ uint cvt2(float a, float b) {
    uint r; asm("cvt.rn.bf16x2.f32 %0, %1, %2;" : "=r"(r) : "f"(b), "f"(a)); return r;
}
__device__ __forceinline__ void ldsm4(uint* r, uint addr) {
    asm volatile("ldmatrix.sync.aligned.m8n8.x4.shared.b16 {%0,%1,%2,%3}, [%4];"
                 : "=r"(r[0]), "=r"(r[1]), "=r"(r[2]), "=r"(r[3]) : "r"(addr));
}
__device__ __forceinline__ void mma16816(float* c, const uint* a, uint b0, uint b1) {
    asm volatile("mma.sync.aligned.m16n8k16.row.col.f32.bf16.bf16.f32 "
                 "{%0,%1,%2,%3}, {%4,%5,%6,%7}, {%8,%9}, {%0,%1,%2,%3};"
                 : "+f"(c[0]), "+f"(c[1]), "+f"(c[2]), "+f"(c[3])
                 : "r"(a[0]), "r"(a[1]), "r"(a[2]), "r"(a[3]), "r"(b0), "r"(b1));
}
__device__ __forceinline__ void split4(float4 v, uint& h01, uint& h23,
                                       uint& l01, uint& l23) {
    h01 = cvt2(v.x, v.y); h23 = cvt2(v.z, v.w);
    float f0 = __uint_as_float(h01 << 16);
    float f1 = __uint_as_float(h01 & 0xFFFF0000u);
    float f2 = __uint_as_float(h23 << 16);
    float f3 = __uint_as_float(h23 & 0xFFFF0000u);
    l01 = cvt2(v.x - f0, v.y - f1); l23 = cvt2(v.z - f2, v.w - f3);
}

// ---------------------------------------------------------------------------
// K0: C_q = E @ W_dec_q + b_dec_q ; E^2.  grid (64, 8), 256 thr, 1 out/thread.
// ---------------------------------------------------------------------------
__global__ __launch_bounds__(256) void k_precompute(const float* __restrict__ E,
                                                    const float* __restrict__ Wdq,
                                                    const float* __restrict__ bdq) {
    __shared__ float Es[Ld];
    int c = blockIdx.x;
    int d = blockIdx.y * 256 + threadIdx.x;
    if (threadIdx.x < Ld) Es[threadIdx.x] = E[c * Ld + threadIdx.x];
    __syncthreads();
    float acc = bdq[d];
#pragma unroll
    for (int l = 0; l < Ld; l++) acc = fmaf(Es[l], Wdq[l * Dd + d], acc);
    g_Cq[c * Dd + d] = acc;
    if (blockIdx.y == 0 && threadIdx.x == 0) {
        float s = 0.f;
#pragma unroll
        for (int l = 0; l < Ld; l++) s = fmaf(Es[l], Es[l], s);
        g_Esq[c] = s;
    }
}

// ---------------------------------------------------------------------------
// K_wsplit: W_enc [2048][64] -> g_Wth/g_Wtl [64][2048]
// ---------------------------------------------------------------------------
__global__ void k_wsplit(const float* __restrict__ Wenc) {
    int idx = blockIdx.x * 256 + threadIdx.x;
    int k = idx >> 6, n = idx & 63;
    float w = Wenc[idx];
    __nv_bfloat16 h = __float2bfloat16(w);
    g_Wth[n * Dd + k] = h;
    g_Wtl[n * Dd + k] = __float2bfloat16(w - __bfloat162float(h));
}

// ---------------------------------------------------------------------------
// K1: z_e = x @ W_enc + b_enc  via mma.sync bf16, 3-term split.
// M-tile 32, grid 1024 (~7 CTA/SM), 128 thr / 4 warps.
// Warp w: row slab s=w>>1 (16 rows), n-half h=w&1 (32 cols)  [R10-validated].
// A-register prefetch depth 2 (LDG chunk c+2 while computing chunk c).
// Per-buffer smem (14336B): A_hi[0,2K) A_lo[2K,4K) B_hi[4K,9.25K) B_lo[9.25K,14.25K)
// ---------------------------------------------------------------------------
__global__ __launch_bounds__(128) void k_enc_mma(const float* __restrict__ x,
                                                 const float* __restrict__ benc,
                                                 float* __restrict__ ze) {
    __shared__ __align__(128) unsigned char SM[2][14336];
    int tid = threadIdx.x;
    int w = tid >> 5, t = tid & 31;
    int s = w >> 1, h = w & 1;
    int row0 = blockIdx.x * 32;
    uint sb = (uint)__cvta_generic_to_shared(SM);

    float acc[4][4];
#pragma unroll
    for (int i = 0; i < 4; i++)
#pragma unroll
        for (int j = 0; j < 4; j++) acc[i][j] = 0.f;

    float4 aregs[2][2];   // [depth][2 f4/thread], chunks c and c+1
#pragma unroll
    for (int d = 0; d < 2; d++)
#pragma unroll
        for (int i = 0; i < 2; i++) {
            int idx = tid + 128 * i;           // 0..255
            int r = idx >> 3, q = idx & 7;
            aregs[d][i] = *(const float4*)&x[(size_t)(row0 + r) * Dd + d * 32 + q * 4];
        }
    // B chunk 0
#pragma unroll
    for (int i = 0; i < 2; i++) {
        int idx = tid + 128 * i;               // 0..255
        int n = idx >> 2, u = idx & 3;
        cp16(&SM[0][4096 + n * 80 + u * 16], &g_Wth[n * Dd + u * 8]);
        cp16(&SM[0][9216 + n * 80 + u * 16], &g_Wtl[n * Dd + u * 8]);
    }
    CP_COMMIT;

    for (int c = 0; c < 64; c++) {
        int p = c & 1;
        uint base = sb + p * 14336;

        // split aregs[p] (chunk c) -> SM[p] A region
#pragma unroll
        for (int i = 0; i < 2; i++) {
            int idx = tid + 128 * i;
            int r = idx >> 3, q = idx & 7;
            uint h01, h23, l01, l23;
            split4(aregs[p][i], h01, h23, l01, l23);
            uint off = (uint)(r * 64 + (((q >> 1) ^ ((r >> 1) & 3)) << 4) + (q & 1) * 8);
            *(uint2*)(&SM[p][off]) = make_uint2(h01, h23);
            *(uint2*)(&SM[p][2048 + off]) = make_uint2(l01, l23);
        }
        // refill aregs[p] with chunk c+2 (deep prefetch)
        if (c < 62) {
#pragma unroll
            for (int i = 0; i < 2; i++) {
                int idx = tid + 128 * i;
                int r = idx >> 3, q = idx & 7;
                aregs[p][i] = *(const float4*)&x[(size_t)(row0 + r) * Dd + (c + 2) * 32 + q * 4];
            }
        }
        CP_WAIT0;            // B chunk c resident
        __syncthreads();

        if (c < 63) {        // B chunk c+1 into other buffer
            unsigned char* bb = SM[p ^ 1];
#pragma unroll
            for (int i = 0; i < 2; i++) {
                int idx = tid + 128 * i;
                int n = idx >> 2, u = idx & 3;
                cp16(bb + 4096 + n * 80 + u * 16, &g_Wth[n * Dd + (c + 1) * 32 + u * 8]);
                cp16(bb + 9216 + n * 80 + u * 16, &g_Wtl[n * Dd + (c + 1) * 32 + u * 8]);
            }
            CP_COMMIT;
        }

        // compute chunk c: warp = 16 rows x 32 cols
        int r = s * 16 + (t & 15);
#pragma unroll
        for (int ks = 0; ks < 2; ks++) {
            uint ua = (uint)((2 * ks + (t >> 4)) ^ ((r >> 1) & 3));
            uint aaddr = base + (uint)(r * 64) + (ua << 4);
            uint ah[4], al[4];
            ldsm4(ah, aaddr);
            ldsm4(al, aaddr + 2048);
#pragma unroll
            for (int np = 0; np < 2; np++) {
                int n = h * 32 + np * 16 + ((t >> 4) & 1) * 8 + (t & 7);
                uint boff = base + 4096u + (uint)(n * 80 + ks * 32 + ((t >> 3) & 1) * 16);
                uint bh[4], bl[4];
                ldsm4(bh, boff);
                ldsm4(bl, boff + 5120);
                mma16816(acc[2 * np], ah, bh[0], bh[1]);
                mma16816(acc[2 * np], al, bh[0], bh[1]);
                mma16816(acc[2 * np], ah, bl[0], bl[1]);
                mma16816(acc[2 * np + 1], ah, bh[2], bh[3]);
                mma16816(acc[2 * np + 1], al, bh[2], bh[3]);
                mma16816(acc[2 * np + 1], ah, bl[2], bl[3]);
            }
        }
    }

    // epilogue: rows s*16 + t/4 (+8), cols h*32 + nt*8 + (t%4)*2 + {0,1}
    int rowA = row0 + s * 16 + (t >> 2);
    int colb = (t & 3) * 2;
#pragma unroll
    for (int nt = 0; nt < 4; nt++) {
        int col = h * 32 + nt * 8 + colb;
        float2 be = *(const float2*)&benc[col];
        *(float2*)&ze[(size_t)rowA * Ld + col] =
            make_float2(acc[nt][0] + be.x, acc[nt][1] + be.y);
        *(float2*)&ze[(size_t)(rowA + 8) * Ld + col] =
            make_float2(acc[nt][2] + be.x, acc[nt][3] + be.y);
    }
}

// ---------------------------------------------------------------------------
// K_assign: 2 threads per row (64-thr block = 32 rows, grid 1024).
// Each thread scores 32 codes; argmin merged via shfl_xor(1) with
// lower-index tie-break (exact first-min). Epilogue split 48/48 f4.
// ---------------------------------------------------------------------------
#define EP 68
__global__ __launch_bounds__(64) void k_assign(const float* __restrict__ ze,
                                               const float* __restrict__ E,
                                               float* __restrict__ zq,
                                               float* __restrict__ nb,
                                               float* __restrict__ kout,
                                               float* __restrict__ zdist) {
    __shared__ float Es[NC][EP];
    __shared__ float Esq_s[NC];
    int tid = threadIdx.x;
#pragma unroll
    for (int i = 0; i < 16; i++) {
        int idx = tid + i * 64;            // 1024 float4s
        int r = idx >> 4, q = idx & 15;
        *(float4*)&Es[r][q * 4] = ((const float4*)E)[idx];
    }
    Esq_s[tid] = g_Esq[tid];
    __syncthreads();

    int rlocal = tid >> 1, half = tid & 1;
    int row = blockIdx.x * 32 + rlocal;
    const float* zr = ze + (size_t)row * Ld;
    float4 z4[16];
#pragma unroll
    for (int j = 0; j < 16; j++) z4[j] = *(const float4*)&zr[j * 4];
    float ze2 = 0.f;
#pragma unroll
    for (int j = 0; j < 16; j++) {
        ze2 = fmaf(z4[j].x, z4[j].x, ze2);
        ze2 = fmaf(z4[j].y, z4[j].y, ze2);
        ze2 = fmaf(z4[j].z, z4[j].z, ze2);
        ze2 = fmaf(z4[j].w, z4[j].w, ze2);
    }

    float best = 3.4e38f; int bk = 0;
    float* zd = zdist + (size_t)row * NC;
    int cb = half * 32;
    for (int c0 = 0; c0 < 32; c0 += 4) {
        float dvals[4];
#pragma unroll
        for (int u = 0; u < 4; u++) {
            int c = cb + c0 + u;
            float dot = 0.f;
#pragma unroll
            for (int j = 0; j < 16; j++) {
                float4 e = *(const float4*)&Es[c][j * 4];
                dot = fmaf(z4[j].x, e.x, dot);
                dot = fmaf(z4[j].y, e.y, dot);
                dot = fmaf(z4[j].z, e.z, dot);
                dot = fmaf(z4[j].w, e.w, dot);
            }
            float dcur = ze2 - 2.f * dot + Esq_s[c];
            dvals[u] = dcur;
            if (dcur < best) { best = dcur; bk = c; }
        }
        *(float4*)&zd[cb + c0] = make_float4(dvals[0], dvals[1], dvals[2], dvals[3]);
    }

    // merge argmin across the pair (disjoint ordered ranges -> exact first-min)
    {
        float ob = __shfl_xor_sync(0xFFFFFFFFu, best, 1);
        int obk = __shfl_xor_sync(0xFFFFFFFFu, bk, 1);
        if (ob < best || (ob == best && obk < bk)) { best = ob; bk = obk; }
    }
    int k1 = bk >> 3, k2 = bk & 7;

    float* zqr = zq + (size_t)row * Ld;
    float* nbr = nb + (size_t)row * 5 * Ld;
    const float4 zero4 = make_float4(0.f, 0.f, 0.f, 0.f);

    if (half == 0) {
        kout[row] = (float)bk;
        g_k[row] = bk;
        const float4* eb = (const float4*)&Es[bk][0];
#pragma unroll
        for (int j = 0; j < 16; j++) {
            float4 v = eb[j];
            *(float4*)&zqr[j * 4] = v;          // z_q
            *(float4*)&nbr[j * 4] = v;          // slot 0
        }
        {   // up: k1 < 7 ? E[k1+1][k2] : 0
            bool ok = (k1 < 7); int idx = ok ? ((k1 + 1) * 8 + k2) : 0;
            const float4* e = (const float4*)&Es[idx][0];
#pragma unroll
            for (int j = 0; j < 16; j++) *(float4*)&nbr[64 + j * 4] = ok ? e[j] : zero4;
        }
    } else {
        {   // down: k1 > 0 ? E[k1-1][k2] : 0
            bool ok = (k1 > 0); int idx = ok ? ((k1 - 1) * 8 + k2) : 0;
            const float4* e = (const float4*)&Es[idx][0];
#pragma unroll
            for (int j = 0; j < 16; j++) *(float4*)&nbr[128 + j * 4] = ok ? e[j] : zero4;
        }
        {   // right: always zero (reference `==` bug)
#pragma unroll
            for (int j = 0; j < 16; j++) *(float4*)&nbr[192 + j * 4] = zero4;
        }
        {   // left: k2 > 0 ? E[k1][k2-1] : 0
            bool ok = (k2 > 0); int idx = ok ? (k1 * 8 + k2 - 1) : 0;
            const float4* e = (const float4*)&Es[idx][0];
#pragma unroll
            for (int j = 0; j < 16; j++) *(float4*)&nbr[256 + j * 4] = ok ? e[j] : zero4;
        }
    }
}

// ---------------------------------------------------------------------------
// K2: x_e = z_e@W_dec_e + b  (R4 scalar FFMA2 config, measured 176us)
//     + fused x_q gather. 256 thr, 128x64 tile, grid (256, 32).
// ---------------------------------------------------------------------------
__device__ __forceinline__ int asw(int row, int u) {   // u = 16B unit 0..15
    return row * 64 + ((u ^ ((row >> 3) & 1)) << 2);
}

__global__ __launch_bounds__(256, 2) void k_dec(const float* __restrict__ ze,
                                                const float* __restrict__ Wde,
                                                const float* __restrict__ bde,
                                                float* __restrict__ xe,
                                                float* __restrict__ xq) {
    __shared__ float As[128 * 64];
    __shared__ float Bs[64][64];
    int tid = threadIdx.x;
    int tx = tid & 15, ty = tid >> 4;
    int row0 = blockIdx.x * 128, c0 = blockIdx.y * 64;

#pragma unroll
    for (int j = 0; j < 8; j++) {
        int idx = tid + 256 * j;
        int r = idx >> 4, u = idx & 15;
        cp16(&As[asw(r, u)], &ze[(size_t)(row0 + r) * Ld + u * 4]);
    }
#pragma unroll
    for (int j = 0; j < 4; j++) {
        int idx = tid + 256 * j;
        int kk = idx >> 4, c4 = (idx & 15) * 4;
        cp16(&Bs[kk][c4], &Wde[(size_t)kk * Dd + c0 + c4]);
    }
    CP_COMMIT;
    CP_WAIT0;
    __syncthreads();

    ull acc[8][2] = {};
#pragma unroll
    for (int k4 = 0; k4 < 64; k4 += 4) {
        float4 a4[8];
#pragma unroll
        for (int r = 0; r < 8; r++)
            a4[r] = *(const float4*)&As[asw(ty * 8 + r, k4 >> 2)];
#pragma unroll
        for (int j = 0; j < 4; j++) {
            ull b0 = *(const ull*)&Bs[k4 + j][4 * tx];
            ull b1 = *(const ull*)&Bs[k4 + j][4 * tx + 2];
#pragma unroll
            for (int r = 0; r < 8; r++) {
                float av = (j == 0) ? a4[r].x : (j == 1) ? a4[r].y
                         : (j == 2) ? a4[r].z : a4[r].w;
                ull a2 = pack2(av);
                ffma2(acc[r][0], a2, b0);
                ffma2(acc[r][1], a2, b1);
            }
        }
    }

    int rowb = row0 + ty * 8;
    int col = c0 + 4 * tx;
    float4 be = *(const float4*)&bde[col];
    int krow[8];
#pragma unroll
    for (int r = 0; r < 8; r++) krow[r] = g_k[rowb + r];
#pragma unroll
    for (int r = 0; r < 8; r++) {
        F2U u0, u1; u0.u = acc[r][0]; u1.u = acc[r][1];
        float4 o = make_float4(u0.f.x + be.x, u0.f.y + be.y,
                               u1.f.x + be.z, u1.f.y + be.w);
        *(float4*)&xe[(size_t)(rowb + r) * Dd + col] = o;
        *(float4*)&xq[(size_t)(rowb + r) * Dd + col] =
            *(const float4*)&g_Cq[(size_t)krow[r] * Dd + col];
    }
}

// ---------------------------------------------------------------------------
extern "C" void kernel_launch(void* const* d_in, const int* in_sizes, int n_in,
                              void* d_out, int out_size) {
    const float* x    = (const float*)d_in[0];
    const float* Wenc = (const float*)d_in[1];
    const float* benc = (const float*)d_in[2];
    const float* Wdq  = (const float*)d_in[3];
    const float* bdq  = (const float*)d_in[4];
    const float* Wde  = (const float*)d_in[5];
    const float* bde  = (const float*)d_in[6];
    const float* E    = (const float*)d_in[7];
    float* out = (float*)d_out;

    const size_t OFF_XE = 0;
    const size_t OFF_XQ = (size_t)Bz * Dd;
    const size_t OFF_ZE = 2 * (size_t)Bz * Dd;
    const size_t OFF_ZQ = OFF_ZE + (size_t)Bz * Ld;
    const size_t OFF_NB = OFF_ZQ + (size_t)Bz * Ld;
    const size_t OFF_K  = OFF_NB + (size_t)Bz * 5 * Ld;
    const size_t OFF_ZD = OFF_K + (size_t)Bz;

    k_wsplit<<<(Dd * Ld) / 256, 256>>>(Wenc);
    k_precompute<<<dim3(NC, 8), 256>>>(E, Wdq, bdq);
    k_enc_mma<<<Bz / 32, 128>>>(x, benc, out + OFF_ZE);
    k_assign<<<Bz / 32, 64>>>(out + OFF_ZE, E,
                              out + OFF_ZQ, out + OFF_NB,
                              out + OFF_K, out + OFF_ZD);
    k_dec<<<dim3(Bz / 128, Dd / 64), 256>>>(out + OFF_ZE, Wde, bde,
                                            out + OFF_XE, out + OFF_XQ);
}

// round 14
// speedup vs baseline: 1.1484x; 1.1484x over previous
#include <cuda_runtime.h>
#include <cuda_bf16.h>

#define Bz 32768
#define Dd 2048
#define Ld 64
#define NC 64
#define EP 68

typedef unsigned long long ull;
typedef unsigned int uint;

static __device__ float g_Cq[NC * Dd];
static __device__ float g_Esq[NC];
static __device__ int   g_k[Bz];
static __device__ __nv_bfloat16 g_Wth[Ld * Dd];  // W_enc^T hi  [64][2048]
static __device__ __nv_bfloat16 g_Wtl[Ld * Dd];  // W_enc^T lo

union F2U { ull u; float2 f; };

__device__ __forceinline__ void ffma2(ull& d, ull a, ull b) {
    asm("fma.rn.f32x2 %0, %1, %2, %0;" : "+l"(d) : "l"(a), "l"(b));
}
__device__ __forceinline__ ull pack2(float a) {
    ull r; asm("mov.b64 %0, {%1, %1};" : "=l"(r) : "f"(a)); return r;
}
__device__ __forceinline__ void cp16(void* s, const void* g) {
    uint sa = (uint)__cvta_generic_to_shared(s);
    asm volatile("cp.async.cg.shared.global [%0], [%1], 16;" :: "r"(sa), "l"(g));
}
#define CP_COMMIT asm volatile("cp.async.commit_group;")
#define CP_WAIT0  asm volatile("cp.async.wait_group 0;")

// packed bf16x2: low half = a, high half = b
__device__ __forceinline__ uint cvt2(float a, float b) {
    uint r; asm("cvt.rn.bf16x2.f32 %0, %1, %2;" : "=r"(r) : "f"(b), "f"(a)); return r;
}
__device__ __forceinline__ void ldsm4(uint* r, uint addr) {
    asm volatile("ldmatrix.sync.aligned.m8n8.x4.shared.b16 {%0,%1,%2,%3}, [%4];"
                 : "=r"(r[0]), "=r"(r[1]), "=r"(r[2]), "=r"(r[3]) : "r"(addr));
}
__device__ __forceinline__ void mma16816(float* c, const uint* a, uint b0, uint b1) {
    asm volatile("mma.sync.aligned.m16n8k16.row.col.f32.bf16.bf16.f32 "
                 "{%0,%1,%2,%3}, {%4,%5,%6,%7}, {%8,%9}, {%0,%1,%2,%3};"
                 : "+f"(c[0]), "+f"(c[1]), "+f"(c[2]), "+f"(c[3])
                 : "r"(a[0]), "r"(a[1]), "r"(a[2]), "r"(a[3]), "r"(b0), "r"(b1));
}
__device__ __forceinline__ void split4(float4 v, uint& h01, uint& h23,
                                       uint& l01, uint& l23) {
    h01 = cvt2(v.x, v.y); h23 = cvt2(v.z, v.w);
    float f0 = __uint_as_float(h01 << 16);
    float f1 = __uint_as_float(h01 & 0xFFFF0000u);
    float f2 = __uint_as_float(h23 << 16);
    float f3 = __uint_as_float(h23 & 0xFFFF0000u);
    l01 = cvt2(v.x - f0, v.y - f1); l23 = cvt2(v.z - f2, v.w - f3);
}

// ---------------------------------------------------------------------------
// K0: C_q = E @ W_dec_q + b_dec_q ; E^2.  grid (64, 8), 256 thr, 1 out/thread.
// ---------------------------------------------------------------------------
__global__ __launch_bounds__(256) void k_precompute(const float* __restrict__ E,
                                                    const float* __restrict__ Wdq,
                                                    const float* __restrict__ bdq) {
    __shared__ float Es[Ld];
    int c = blockIdx.x;
    int d = blockIdx.y * 256 + threadIdx.x;
    if (threadIdx.x < Ld) Es[threadIdx.x] = E[c * Ld + threadIdx.x];
    __syncthreads();
    float acc = bdq[d];
#pragma unroll
    for (int l = 0; l < Ld; l++) acc = fmaf(Es[l], Wdq[l * Dd + d], acc);
    g_Cq[c * Dd + d] = acc;
    if (blockIdx.y == 0 && threadIdx.x == 0) {
        float s = 0.f;
#pragma unroll
        for (int l = 0; l < Ld; l++) s = fmaf(Es[l], Es[l], s);
        g_Esq[c] = s;
    }
}

// ---------------------------------------------------------------------------
// K_wsplit: W_enc [2048][64] -> g_Wth/g_Wtl [64][2048]
// ---------------------------------------------------------------------------
__global__ void k_wsplit(const float* __restrict__ Wenc) {
    int idx = blockIdx.x * 256 + threadIdx.x;
    int k = idx >> 6, n = idx & 63;
    float w = Wenc[idx];
    __nv_bfloat16 h = __float2bfloat16(w);
    g_Wth[n * Dd + k] = h;
    g_Wtl[n * Dd + k] = __float2bfloat16(w - __bfloat162float(h));
}

// ---------------------------------------------------------------------------
// K1: FUSED  z_e = x@W_enc + b_enc (R7 mma mainloop, 64-row tile, grid 512)
//     + distances/argmin/z_q/neighbors/k/z_dist for the same 64 rows.
// After the mainloop the 36KB stage buffers are reused as:
//   zs  [64][68] f32 @ 0       (17408 B)
//   Es  [64][68] f32 @ 17408   (17408 B)
//   Esq [64]     f32 @ 34816   (256 B)      total 35072 <= 36864
// Assign phase: 2 threads/row (R13-validated shfl merge, exact first-min).
// ---------------------------------------------------------------------------
__global__ __launch_bounds__(128) void k_enc_assign(
        const float* __restrict__ x, const float* __restrict__ benc,
        const float* __restrict__ E,
        float* __restrict__ ze, float* __restrict__ zq,
        float* __restrict__ nb, float* __restrict__ kout,
        float* __restrict__ zdist) {
    __shared__ __align__(128) unsigned char SM[2][18432];
    int tid = threadIdx.x;
    int w = tid >> 5, t = tid & 31;
    int row0 = blockIdx.x * 64;
    uint sb = (uint)__cvta_generic_to_shared(SM);

    float acc[8][4];
#pragma unroll
    for (int i = 0; i < 8; i++)
#pragma unroll
        for (int j = 0; j < 4; j++) acc[i][j] = 0.f;

    float4 aregs[4];
#pragma unroll
    for (int i = 0; i < 4; i++) {
        int idx = tid + 128 * i;
        int r = idx >> 3, q = idx & 7;
        aregs[i] = *(const float4*)&x[(size_t)(row0 + r) * Dd + q * 4];
    }
#pragma unroll
    for (int i = 0; i < 2; i++) {
        int idx = tid + 128 * i;
        int n = idx >> 2, u = idx & 3;
        cp16(&SM[0][8192 + n * 80 + u * 16], &g_Wth[n * Dd + u * 8]);
        cp16(&SM[0][13312 + n * 80 + u * 16], &g_Wtl[n * Dd + u * 8]);
    }
    CP_COMMIT;

    for (int c = 0; c < 64; c++) {
        int p = c & 1;
        uint base = sb + p * 18432;

#pragma unroll
        for (int i = 0; i < 4; i++) {
            int idx = tid + 128 * i;
            int r = idx >> 3, q = idx & 7;
            uint h01, h23, l01, l23;
            split4(aregs[i], h01, h23, l01, l23);
            uint off = (uint)(r * 64 + (((q >> 1) ^ ((r >> 1) & 3)) << 4) + (q & 1) * 8);
            *(uint2*)(&SM[p][off]) = make_uint2(h01, h23);
            *(uint2*)(&SM[p][4096 + off]) = make_uint2(l01, l23);
        }
        CP_WAIT0;
        __syncthreads();

        if (c < 63) {
#pragma unroll
            for (int i = 0; i < 4; i++) {
                int idx = tid + 128 * i;
                int r = idx >> 3, q = idx & 7;
                aregs[i] = *(const float4*)&x[(size_t)(row0 + r) * Dd + (c + 1) * 32 + q * 4];
            }
            unsigned char* bb = SM[p ^ 1];
#pragma unroll
            for (int i = 0; i < 2; i++) {
                int idx = tid + 128 * i;
                int n = idx >> 2, u = idx & 3;
                cp16(bb + 8192 + n * 80 + u * 16, &g_Wth[n * Dd + (c + 1) * 32 + u * 8]);
                cp16(bb + 13312 + n * 80 + u * 16, &g_Wtl[n * Dd + (c + 1) * 32 + u * 8]);
            }
            CP_COMMIT;
        }

        int r = w * 16 + (t & 15);
#pragma unroll
        for (int ks = 0; ks < 2; ks++) {
            uint ua = (uint)((2 * ks + (t >> 4)) ^ ((r >> 1) & 3));
            uint aaddr = base + (uint)(r * 64) + (ua << 4);
            uint ah[4], al[4];
            ldsm4(ah, aaddr);
            ldsm4(al, aaddr + 4096);
#pragma unroll
            for (int np = 0; np < 4; np++) {
                int n = np * 16 + ((t >> 4) & 1) * 8 + (t & 7);
                uint boff = base + 8192u + (uint)(n * 80 + ks * 32 + ((t >> 3) & 1) * 16);
                uint bh[4], bl[4];
                ldsm4(bh, boff);
                ldsm4(bl, boff + 5120);
                mma16816(acc[2 * np], ah, bh[0], bh[1]);
                mma16816(acc[2 * np], al, bh[0], bh[1]);
                mma16816(acc[2 * np], ah, bl[0], bl[1]);
                mma16816(acc[2 * np + 1], ah, bh[2], bh[3]);
                mma16816(acc[2 * np + 1], al, bh[2], bh[3]);
                mma16816(acc[2 * np + 1], ah, bl[2], bl[3]);
            }
        }
    }

    __syncthreads();   // all warps done with stage buffers; reuse as zs/Es

    float* zs   = (float*)SM;                          // [64][EP]
    float* EsF  = (float*)((unsigned char*)SM + 17408); // [64][EP]
    float* EsqF = (float*)((unsigned char*)SM + 34816); // [64]

    // epilogue 1: bias, write ze to global + zs tile in smem
    {
        int rL = w * 16 + (t >> 2);
        int colb = (t & 3) * 2;
#pragma unroll
        for (int nt = 0; nt < 8; nt++) {
            int col = nt * 8 + colb;
            float2 be = *(const float2*)&benc[col];
            float2 o0 = make_float2(acc[nt][0] + be.x, acc[nt][1] + be.y);
            float2 o1 = make_float2(acc[nt][2] + be.x, acc[nt][3] + be.y);
            *(float2*)&ze[(size_t)(row0 + rL) * Ld + col] = o0;
            *(float2*)&ze[(size_t)(row0 + rL + 8) * Ld + col] = o1;
            *(float2*)&zs[rL * EP + col] = o0;
            *(float2*)&zs[(rL + 8) * EP + col] = o1;
        }
    }
    // load Es (padded) + Esq
#pragma unroll
    for (int i = 0; i < 8; i++) {
        int idx = tid + 128 * i;            // 1024 float4s
        int r = idx >> 4, q = idx & 15;
        *(float4*)&EsF[r * EP + q * 4] = ((const float4*)E)[idx];
    }
    if (tid < NC) EsqF[tid] = g_Esq[tid];
    __syncthreads();

    // assign phase: 2 threads per row
    int rlocal = tid >> 1, half = tid & 1;
    int row = row0 + rlocal;
    const float* zr = &zs[rlocal * EP];
    float4 z4[16];
#pragma unroll
    for (int j = 0; j < 16; j++) z4[j] = *(const float4*)&zr[j * 4];
    float ze2 = 0.f;
#pragma unroll
    for (int j = 0; j < 16; j++) {
        ze2 = fmaf(z4[j].x, z4[j].x, ze2);
        ze2 = fmaf(z4[j].y, z4[j].y, ze2);
        ze2 = fmaf(z4[j].z, z4[j].z, ze2);
        ze2 = fmaf(z4[j].w, z4[j].w, ze2);
    }

    float best = 3.4e38f; int bk = 0;
    float* zd = zdist + (size_t)row * NC;
    int cb = half * 32;
    for (int c0 = 0; c0 < 32; c0 += 4) {
        float dvals[4];
#pragma unroll
        for (int u = 0; u < 4; u++) {
            int c = cb + c0 + u;
            float dot = 0.f;
#pragma unroll
            for (int j = 0; j < 16; j++) {
                float4 e = *(const float4*)&EsF[c * EP + j * 4];
                dot = fmaf(z4[j].x, e.x, dot);
                dot = fmaf(z4[j].y, e.y, dot);
                dot = fmaf(z4[j].z, e.z, dot);
                dot = fmaf(z4[j].w, e.w, dot);
            }
            float dcur = ze2 - 2.f * dot + EsqF[c];
            dvals[u] = dcur;
            if (dcur < best) { best = dcur; bk = c; }
        }
        *(float4*)&zd[cb + c0] = make_float4(dvals[0], dvals[1], dvals[2], dvals[3]);
    }

    // merge argmin across pair (disjoint ordered ranges -> exact first-min)
    {
        float ob = __shfl_xor_sync(0xFFFFFFFFu, best, 1);
        int obk = __shfl_xor_sync(0xFFFFFFFFu, bk, 1);
        if (ob < best || (ob == best && obk < bk)) { best = ob; bk = obk; }
    }
    int k1 = bk >> 3, k2 = bk & 7;

    float* zqr = zq + (size_t)row * Ld;
    float* nbr = nb + (size_t)row * 5 * Ld;
    const float4 zero4 = make_float4(0.f, 0.f, 0.f, 0.f);

    if (half == 0) {
        kout[row] = (float)bk;
        g_k[row] = bk;
        const float* eb = &EsF[bk * EP];
#pragma unroll
        for (int j = 0; j < 16; j++) {
            float4 v = *(const float4*)&eb[j * 4];
            *(float4*)&zqr[j * 4] = v;
            *(float4*)&nbr[j * 4] = v;
        }
        {   // up
            bool ok = (k1 < 7); int idx = ok ? ((k1 + 1) * 8 + k2) : 0;
            const float* e = &EsF[idx * EP];
#pragma unroll
            for (int j = 0; j < 16; j++)
                *(float4*)&nbr[64 + j * 4] = ok ? *(const float4*)&e[j * 4] : zero4;
        }
    } else {
        {   // down
            bool ok = (k1 > 0); int idx = ok ? ((k1 - 1) * 8 + k2) : 0;
            const float* e = &EsF[idx * EP];
#pragma unroll
            for (int j = 0; j < 16; j++)
                *(float4*)&nbr[128 + j * 4] = ok ? *(const float4*)&e[j * 4] : zero4;
        }
        {   // right: always zero (reference `==` bug)
#pragma unroll
            for (int j = 0; j < 16; j++) *(float4*)&nbr[192 + j * 4] = zero4;
        }
        {   // left
            bool ok = (k2 > 0); int idx = ok ? (k1 * 8 + k2 - 1) : 0;
            const float* e = &EsF[idx * EP];
#pragma unroll
            for (int j = 0; j < 16; j++)
                *(float4*)&nbr[256 + j * 4] = ok ? *(const float4*)&e[j * 4] : zero4;
        }
    }
}

// ---------------------------------------------------------------------------
// K2: x_e = z_e@W_dec_e + b  (R4 scalar FFMA2 config, measured 176us)
//     + fused x_q gather. 256 thr, 128x64 tile, grid (256, 32).
// ---------------------------------------------------------------------------
__device__ __forceinline__ int asw(int row, int u) {   // u = 16B unit 0..15
    return row * 64 + ((u ^ ((row >> 3) & 1)) << 2);
}

__global__ __launch_bounds__(256, 2) void k_dec(const float* __restrict__ ze,
                                                const float* __restrict__ Wde,
                                                const float* __restrict__ bde,
                                                float* __restrict__ xe,
                                                float* __restrict__ xq) {
    __shared__ float As[128 * 64];
    __shared__ float Bs[64][64];
    int tid = threadIdx.x;
    int tx = tid & 15, ty = tid >> 4;
    int row0 = blockIdx.x * 128, c0 = blockIdx.y * 64;

#pragma unroll
    for (int j = 0; j < 8; j++) {
        int idx = tid + 256 * j;
        int r = idx >> 4, u = idx & 15;
        cp16(&As[asw(r, u)], &ze[(size_t)(row0 + r) * Ld + u * 4]);
    }
#pragma unroll
    for (int j = 0; j < 4; j++) {
        int idx = tid + 256 * j;
        int kk = idx >> 4, c4 = (idx & 15) * 4;
        cp16(&Bs[kk][c4], &Wde[(size_t)kk * Dd + c0 + c4]);
    }
    CP_COMMIT;
    CP_WAIT0;
    __syncthreads();

    ull acc[8][2] = {};
#pragma unroll
    for (int k4 = 0; k4 < 64; k4 += 4) {
        float4 a4[8];
#pragma unroll
        for (int r = 0; r < 8; r++)
            a4[r] = *(const float4*)&As[asw(ty * 8 + r, k4 >> 2)];
#pragma unroll
        for (int j = 0; j < 4; j++) {
            ull b0 = *(const ull*)&Bs[k4 + j][4 * tx];
            ull b1 = *(const ull*)&Bs[k4 + j][4 * tx + 2];
#pragma unroll
            for (int r = 0; r < 8; r++) {
                float av = (j == 0) ? a4[r].x : (j == 1) ? a4[r].y
                         : (j == 2) ? a4[r].z : a4[r].w;
                ull a2 = pack2(av);
                ffma2(acc[r][0], a2, b0);
                ffma2(acc[r][1], a2, b1);
            }
        }
    }

    int rowb = row0 + ty * 8;
    int col = c0 + 4 * tx;
    float4 be = *(const float4*)&bde[col];
    int krow[8];
#pragma unroll
    for (int r = 0; r < 8; r++) krow[r] = g_k[rowb + r];
#pragma unroll
    for (int r = 0; r < 8; r++) {
        F2U u0, u1; u0.u = acc[r][0]; u1.u = acc[r][1];
        float4 o = make_float4(u0.f.x + be.x, u0.f.y + be.y,
                               u1.f.x + be.z, u1.f.y + be.w);
        *(float4*)&xe[(size_t)(rowb + r) * Dd + col] = o;
        *(float4*)&xq[(size_t)(rowb + r) * Dd + col] =
            *(const float4*)&g_Cq[(size_t)krow[r] * Dd + col];
    }
}

// ---------------------------------------------------------------------------
extern "C" void kernel_launch(void* const* d_in, const int* in_sizes, int n_in,
                              void* d_out, int out_size) {
    const float* x    = (const float*)d_in[0];
    const float* Wenc = (const float*)d_in[1];
    const float* benc = (const float*)d_in[2];
    const float* Wdq  = (const float*)d_in[3];
    const float* bdq  = (const float*)d_in[4];
    const float* Wde  = (const float*)d_in[5];
    const float* bde  = (const float*)d_in[6];
    const float* E    = (const float*)d_in[7];
    float* out = (float*)d_out;

    const size_t OFF_XE = 0;
    const size_t OFF_XQ = (size_t)Bz * Dd;
    const size_t OFF_ZE = 2 * (size_t)Bz * Dd;
    const size_t OFF_ZQ = OFF_ZE + (size_t)Bz * Ld;
    const size_t OFF_NB = OFF_ZQ + (size_t)Bz * Ld;
    const size_t OFF_K  = OFF_NB + (size_t)Bz * 5 * Ld;
    const size_t OFF_ZD = OFF_K + (size_t)Bz;

    k_wsplit<<<(Dd * Ld) / 256, 256>>>(Wenc);
    k_precompute<<<dim3(NC, 8), 256>>>(E, Wdq, bdq);
    k_enc_assign<<<Bz / 64, 128>>>(x, benc, E, out + OFF_ZE,
                                   out + OFF_ZQ, out + OFF_NB,
                                   out + OFF_K, out + OFF_ZD);
    k_dec<<<dim3(Bz / 128, Dd / 64), 256>>>(out + OFF_ZE, Wde, bde,
                                            out + OFF_XE, out + OFF_XQ);
}